// round 1
// baseline (speedup 1.0000x reference)
#include <cuda_runtime.h>
#include <math.h>

#define SEQ 4096
#define DIM 1024

// Scratch (no-alloc rule: __device__ globals)
__device__ float g_Q[SEQ * DIM];
__device__ float g_K[SEQ * DIM];
__device__ float g_V[SEQ * DIM];
__device__ float g_S[(size_t)SEQ * SEQ];

// ---------------------------------------------------------------------------
// Generic tiled fp32 GEMM: C[M,N] = alpha * A[M,K] @ op(B) + bias
//   TRANS_B = 0: B is [K,N] row-major
//   TRANS_B = 1: B is [N,K] row-major (C = alpha * A @ B^T)
// Tile: BM=BN=128, BK=16, 256 threads, 8x8 micro-tile per thread.
// All problem dims here are multiples of 128/16 -> no edge handling.
// ---------------------------------------------------------------------------
template <int TRANS_B>
__global__ __launch_bounds__(256) void gemm_kernel(
    const float* __restrict__ A, const float* __restrict__ B,
    const float* __restrict__ bias, float* __restrict__ C,
    int M, int N, int K, float alpha)
{
    __shared__ float As[16][128];
    __shared__ float Bs[16][128];

    const int tid = threadIdx.x;
    const int bm = blockIdx.y * 128;
    const int bn = blockIdx.x * 128;

    const int tx = tid & 15;   // 0..15 -> column group (8 cols each)
    const int ty = tid >> 4;   // 0..15 -> row group (8 rows each)

    float acc[8][8];
    #pragma unroll
    for (int i = 0; i < 8; i++)
        #pragma unroll
        for (int j = 0; j < 8; j++) acc[i][j] = 0.0f;

    float a_frag[8], b_frag[8];

    for (int k0 = 0; k0 < K; k0 += 16) {
        // ---- Load A tile: rows [bm, bm+128), cols [k0, k0+16) -> As[k][m]
        {
            const int r = tid >> 2;          // 0..63
            const int c = (tid & 3) << 2;    // 0,4,8,12
            #pragma unroll
            for (int rr = 0; rr < 128; rr += 64) {
                float4 v = *reinterpret_cast<const float4*>(
                    &A[(size_t)(bm + r + rr) * K + k0 + c]);
                As[c + 0][r + rr] = v.x;
                As[c + 1][r + rr] = v.y;
                As[c + 2][r + rr] = v.z;
                As[c + 3][r + rr] = v.w;
            }
        }
        // ---- Load B tile -> Bs[k][n]
        if (TRANS_B) {
            // B is [N,K]: Bs[k][n] = B[bn+n][k0+k]
            const int r = tid >> 2;
            const int c = (tid & 3) << 2;
            #pragma unroll
            for (int rr = 0; rr < 128; rr += 64) {
                float4 v = *reinterpret_cast<const float4*>(
                    &B[(size_t)(bn + r + rr) * K + k0 + c]);
                Bs[c + 0][r + rr] = v.x;
                Bs[c + 1][r + rr] = v.y;
                Bs[c + 2][r + rr] = v.z;
                Bs[c + 3][r + rr] = v.w;
            }
        } else {
            // B is [K,N]: Bs[k][n] = B[k0+k][bn+n]
            const int r = tid >> 5;          // 0..7
            const int c = (tid & 31) << 2;   // 0..124
            #pragma unroll
            for (int rr = 0; rr < 16; rr += 8) {
                float4 v = *reinterpret_cast<const float4*>(
                    &B[(size_t)(k0 + r + rr) * N + bn + c]);
                *reinterpret_cast<float4*>(&Bs[r + rr][c]) = v;
            }
        }
        __syncthreads();

        // ---- Compute
        #pragma unroll
        for (int k = 0; k < 16; k++) {
            #pragma unroll
            for (int i = 0; i < 8; i++) a_frag[i] = As[k][ty * 8 + i];
            #pragma unroll
            for (int j = 0; j < 8; j++) b_frag[j] = Bs[k][tx * 8 + j];
            #pragma unroll
            for (int i = 0; i < 8; i++)
                #pragma unroll
                for (int j = 0; j < 8; j++)
                    acc[i][j] = fmaf(a_frag[i], b_frag[j], acc[i][j]);
        }
        __syncthreads();
    }

    // ---- Epilogue
    float bfrag[8];
    #pragma unroll
    for (int j = 0; j < 8; j++)
        bfrag[j] = bias ? bias[bn + tx * 8 + j] : 0.0f;

    #pragma unroll
    for (int i = 0; i < 8; i++) {
        const size_t row = (size_t)(bm + ty * 8 + i);
        float4 o0, o1;
        o0.x = alpha * acc[i][0] + bfrag[0];
        o0.y = alpha * acc[i][1] + bfrag[1];
        o0.z = alpha * acc[i][2] + bfrag[2];
        o0.w = alpha * acc[i][3] + bfrag[3];
        o1.x = alpha * acc[i][4] + bfrag[4];
        o1.y = alpha * acc[i][5] + bfrag[5];
        o1.z = alpha * acc[i][6] + bfrag[6];
        o1.w = alpha * acc[i][7] + bfrag[7];
        *reinterpret_cast<float4*>(&C[row * N + bn + tx * 8 + 0]) = o0;
        *reinterpret_cast<float4*>(&C[row * N + bn + tx * 8 + 4]) = o1;
    }
}

// ---------------------------------------------------------------------------
// Row softmax over S[SEQ, SEQ], in place. One block per row.
// ---------------------------------------------------------------------------
__global__ __launch_bounds__(256) void softmax_kernel(float* __restrict__ S, int n)
{
    float* p = S + (size_t)blockIdx.x * n;
    __shared__ float red[256];
    const int tid = threadIdx.x;

    // 1) row max
    float m = -INFINITY;
    for (int i = tid * 4; i < n; i += 256 * 4) {
        float4 v = *reinterpret_cast<const float4*>(&p[i]);
        m = fmaxf(m, fmaxf(fmaxf(v.x, v.y), fmaxf(v.z, v.w)));
    }
    red[tid] = m;
    __syncthreads();
    for (int s = 128; s > 0; s >>= 1) {
        if (tid < s) red[tid] = fmaxf(red[tid], red[tid + s]);
        __syncthreads();
    }
    m = red[0];
    __syncthreads();

    // 2) exp and sum
    float sum = 0.0f;
    for (int i = tid * 4; i < n; i += 256 * 4) {
        float4 v = *reinterpret_cast<const float4*>(&p[i]);
        v.x = expf(v.x - m);
        v.y = expf(v.y - m);
        v.z = expf(v.z - m);
        v.w = expf(v.w - m);
        sum += v.x + v.y + v.z + v.w;
        *reinterpret_cast<float4*>(&p[i]) = v;
    }
    red[tid] = sum;
    __syncthreads();
    for (int s = 128; s > 0; s >>= 1) {
        if (tid < s) red[tid] += red[tid + s];
        __syncthreads();
    }
    const float inv = 1.0f / red[0];
    __syncthreads();

    // 3) normalize
    for (int i = tid * 4; i < n; i += 256 * 4) {
        float4 v = *reinterpret_cast<const float4*>(&p[i]);
        v.x *= inv; v.y *= inv; v.z *= inv; v.w *= inv;
        *reinterpret_cast<float4*>(&p[i]) = v;
    }
}

// ---------------------------------------------------------------------------
// Launch
// ---------------------------------------------------------------------------
extern "C" void kernel_launch(void* const* d_in, const int* in_sizes, int n_in,
                              void* d_out, int out_size)
{
    const float* X  = (const float*)d_in[0];
    const float* Wq = (const float*)d_in[1];
    const float* bq = (const float*)d_in[2];
    const float* Wk = (const float*)d_in[3];
    const float* bk = (const float*)d_in[4];
    const float* Wv = (const float*)d_in[5];
    const float* bv = (const float*)d_in[6];
    float* out = (float*)d_out;

    float *Q, *K, *V, *S;
    cudaGetSymbolAddress((void**)&Q, g_Q);
    cudaGetSymbolAddress((void**)&K, g_K);
    cudaGetSymbolAddress((void**)&V, g_V);
    cudaGetSymbolAddress((void**)&S, g_S);

    const dim3 blk(256);
    const dim3 grid_qkv(DIM / 128, SEQ / 128);   // N x M tiles
    const dim3 grid_ss(SEQ / 128, SEQ / 128);

    // QKV projections
    gemm_kernel<0><<<grid_qkv, blk>>>(X, Wq, bq, Q, SEQ, DIM, DIM, 1.0f);
    gemm_kernel<0><<<grid_qkv, blk>>>(X, Wk, bk, K, SEQ, DIM, DIM, 1.0f);
    gemm_kernel<0><<<grid_qkv, blk>>>(X, Wv, bv, V, SEQ, DIM, DIM, 1.0f);

    // scores = (Q @ K^T) / sqrt(D)
    gemm_kernel<1><<<grid_ss, blk>>>(Q, K, nullptr, S, SEQ, SEQ, DIM, 1.0f / 32.0f);

    // softmax rows
    softmax_kernel<<<SEQ, blk>>>(S, SEQ);

    // out = P @ V
    gemm_kernel<0><<<grid_qkv, blk>>>(S, V, nullptr, out, SEQ, DIM, SEQ, 1.0f);
}

// round 3
// speedup vs baseline: 2.6636x; 2.6636x over previous
#include <cuda_runtime.h>
#include <cuda_bf16.h>
#include <math.h>

#define SEQ 4096
#define DIM 1024

// ---------------------------------------------------------------------------
// Persistent scratch (__device__ globals; no-alloc rule)
// ---------------------------------------------------------------------------
__device__ __nv_bfloat16 g_Xhi[SEQ * DIM];
__device__ __nv_bfloat16 g_Xlo[SEQ * DIM];
__device__ __nv_bfloat16 g_Wthi[3 * DIM * DIM];   // W^T per slot: [n][k]
__device__ __nv_bfloat16 g_Wtlo[3 * DIM * DIM];
__device__ __nv_bfloat16 g_QKVhi[3 * SEQ * DIM];  // Q,K,V row-major [s][d]
__device__ __nv_bfloat16 g_QKVlo[3 * SEQ * DIM];
__device__ __nv_bfloat16 g_Vthi[DIM * SEQ];       // V^T [d][s]
__device__ __nv_bfloat16 g_Vtlo[DIM * SEQ];
__device__ float         g_S[(size_t)SEQ * SEQ];  // scores
__device__ __nv_bfloat16 g_Phi[(size_t)SEQ * SEQ];
__device__ __nv_bfloat16 g_Plo[(size_t)SEQ * SEQ];

// ---------------------------------------------------------------------------
// PTX helpers (baseline sm_103: mma.sync / ldmatrix / cp.async)
// ---------------------------------------------------------------------------
__device__ __forceinline__ unsigned smem_u32(const void* p) {
    unsigned a;
    asm("{ .reg .u64 t; cvta.to.shared.u64 t, %1; cvt.u32.u64 %0, t; }"
        : "=r"(a) : "l"(p));
    return a;
}

__device__ __forceinline__ void cp16(unsigned dst, const void* src) {
    asm volatile("cp.async.cg.shared.global [%0], [%1], 16;"
                 :: "r"(dst), "l"(src));
}
#define CP_COMMIT() asm volatile("cp.async.commit_group;" ::: "memory")
#define CP_WAIT1()  asm volatile("cp.async.wait_group 1;" ::: "memory")

__device__ __forceinline__ void ldm_x4(unsigned* r, unsigned addr) {
    asm volatile("ldmatrix.sync.aligned.m8n8.x4.shared.b16 {%0,%1,%2,%3}, [%4];"
                 : "=r"(r[0]), "=r"(r[1]), "=r"(r[2]), "=r"(r[3]) : "r"(addr));
}

__device__ __forceinline__ void mma4(float* c, const unsigned* a, const unsigned* b) {
    asm volatile(
        "mma.sync.aligned.m16n8k16.row.col.f32.bf16.bf16.f32 "
        "{%0,%1,%2,%3}, {%4,%5,%6,%7}, {%8,%9}, {%0,%1,%2,%3};"
        : "+f"(c[0]), "+f"(c[1]), "+f"(c[2]), "+f"(c[3])
        : "r"(a[0]), "r"(a[1]), "r"(a[2]), "r"(a[3]), "r"(b[0]), "r"(b[1]));
}

// ---------------------------------------------------------------------------
// GEMM: C[M,N] = alpha * Asplit @ Bsplit^T (+bias, split epilogue)
//   A: (m,k) row-major hi/lo bf16, pitch K
//   B: (n,k) row-major hi/lo bf16, pitch K
//   EPI=0: Cf fp32 = alpha*acc
//   EPI=1: split: v = acc + bias[n]; Chi/Clo bf16
// Tile 128x128x32, 8 warps (4m x 2n), warp tile 32x64, 2-stage cp.async.
// SMEM pitch 80 B per 32-half row -> conflict-free ldmatrix.
// ---------------------------------------------------------------------------
#define PITCH      80
#define MAT_BYTES  (128 * PITCH)          // 10240
#define STAGE_BYTES (4 * MAT_BYTES)       // 40960
#define SMEM_BYTES (2 * STAGE_BYTES)      // 81920
#define OFF_AHI 0
#define OFF_ALO MAT_BYTES
#define OFF_BHI (2 * MAT_BYTES)
#define OFF_BLO (3 * MAT_BYTES)

template <int EPI>
__global__ __launch_bounds__(256) void hmma_gemm(
    const __nv_bfloat16* __restrict__ Ahi, const __nv_bfloat16* __restrict__ Alo,
    const __nv_bfloat16* __restrict__ Bhi, const __nv_bfloat16* __restrict__ Blo,
    const float* __restrict__ bias0, const float* __restrict__ bias1,
    const float* __restrict__ bias2,
    float* __restrict__ Cf,
    __nv_bfloat16* __restrict__ Chi, __nv_bfloat16* __restrict__ Clo,
    int M, int N, int K, float alpha, size_t bSlot, size_t cSlot)
{
    extern __shared__ char smem[];
    const unsigned sb = smem_u32(smem);
    const int tid = threadIdx.x;
    const int wid = tid >> 5;
    const int lane = tid & 31;
    const int bm = blockIdx.y * 128;
    const int bn = blockIdx.x * 128;
    const int z = blockIdx.z;

    Bhi += (size_t)z * bSlot;
    Blo += (size_t)z * bSlot;
    const float* bias = (z == 0) ? bias0 : (z == 1) ? bias1 : bias2;

    const int warp_m = wid & 3;   // 0..3 -> 32 rows
    const int warp_n = wid >> 2;  // 0..1 -> 64 cols

    float acc[2][8][4];
    #pragma unroll
    for (int i = 0; i < 2; i++)
        #pragma unroll
        for (int j = 0; j < 8; j++)
            #pragma unroll
            for (int q = 0; q < 4; q++) acc[i][j][q] = 0.0f;

    // ldmatrix per-lane base offsets (bytes within a matrix)
    const unsigned aOff =
        (unsigned)((warp_m * 32 + (lane & 7) + ((lane >> 3) & 1) * 8) * PITCH
                   + (lane >> 4) * 16);
    const unsigned bOff =
        (unsigned)((warp_n * 64 + (lane & 7) + ((lane >> 4) & 1) * 8) * PITCH
                   + ((lane >> 3) & 1) * 16);

    // cp.async stage loader: 2048 16B-chunks, 8 per thread
    auto load_stage = [&](int stg, int kc) {
        const unsigned base = sb + stg * STAGE_BYTES;
        #pragma unroll
        for (int t = 0; t < 8; t++) {
            const int id = tid + t * 256;
            const int mat = id >> 9;          // constant per t
            const int r = (id >> 2) & 127;
            const int c4 = id & 3;
            const __nv_bfloat16* src;
            if (mat == 0)      src = Ahi + (size_t)(bm + r) * K + kc + c4 * 8;
            else if (mat == 1) src = Alo + (size_t)(bm + r) * K + kc + c4 * 8;
            else if (mat == 2) src = Bhi + (size_t)(bn + r) * K + kc + c4 * 8;
            else               src = Blo + (size_t)(bn + r) * K + kc + c4 * 8;
            cp16(base + mat * MAT_BYTES + r * PITCH + c4 * 16, src);
        }
    };

    const int nch = K >> 5;
    load_stage(0, 0);
    CP_COMMIT();

    for (int c = 0; c < nch; c++) {
        if (c + 1 < nch) load_stage((c + 1) & 1, (c + 1) << 5);
        CP_COMMIT();
        CP_WAIT1();
        __syncthreads();

        const unsigned stg = sb + (c & 1) * STAGE_BYTES;
        #pragma unroll
        for (int ks = 0; ks < 2; ks++) {
            unsigned ah[2][4], al[2][4], bh[8][2], bl[8][2];
            #pragma unroll
            for (int im = 0; im < 2; im++) {
                ldm_x4(ah[im], stg + OFF_AHI + aOff + im * (16 * PITCH) + ks * 32);
                ldm_x4(al[im], stg + OFF_ALO + aOff + im * (16 * PITCH) + ks * 32);
            }
            #pragma unroll
            for (int jn = 0; jn < 4; jn++) {
                unsigned r[4];
                ldm_x4(r, stg + OFF_BHI + bOff + jn * (16 * PITCH) + ks * 32);
                bh[jn * 2][0] = r[0]; bh[jn * 2][1] = r[1];
                bh[jn * 2 + 1][0] = r[2]; bh[jn * 2 + 1][1] = r[3];
                ldm_x4(r, stg + OFF_BLO + bOff + jn * (16 * PITCH) + ks * 32);
                bl[jn * 2][0] = r[0]; bl[jn * 2][1] = r[1];
                bl[jn * 2 + 1][0] = r[2]; bl[jn * 2 + 1][1] = r[3];
            }
            #pragma unroll
            for (int im = 0; im < 2; im++)
                #pragma unroll
                for (int j = 0; j < 8; j++) {
                    mma4(acc[im][j], ah[im], bh[j]);
                    mma4(acc[im][j], ah[im], bl[j]);
                    mma4(acc[im][j], al[im], bh[j]);
                }
        }
        __syncthreads();
    }

    // ---- Epilogue ----
    const int r0 = bm + warp_m * 32 + (lane >> 2);
    const int c0 = bn + warp_n * 64 + (lane & 3) * 2;

    if (EPI == 0) {
        Cf += (size_t)z * cSlot;
        #pragma unroll
        for (int im = 0; im < 2; im++)
            #pragma unroll
            for (int j = 0; j < 8; j++) {
                const int row = r0 + im * 16;
                const int col = c0 + j * 8;
                float2 v0 = make_float2(alpha * acc[im][j][0], alpha * acc[im][j][1]);
                float2 v1 = make_float2(alpha * acc[im][j][2], alpha * acc[im][j][3]);
                *reinterpret_cast<float2*>(&Cf[(size_t)row * N + col]) = v0;
                *reinterpret_cast<float2*>(&Cf[(size_t)(row + 8) * N + col]) = v1;
            }
    } else {
        Chi += (size_t)z * cSlot;
        Clo += (size_t)z * cSlot;
        #pragma unroll
        for (int im = 0; im < 2; im++)
            #pragma unroll
            for (int j = 0; j < 8; j++) {
                const int row = r0 + im * 16;
                const int col = c0 + j * 8;
                const float b0 = bias[col], b1 = bias[col + 1];
                #pragma unroll
                for (int h = 0; h < 2; h++) {
                    const int rr = row + h * 8;
                    float v0 = acc[im][j][h * 2 + 0] + b0;
                    float v1 = acc[im][j][h * 2 + 1] + b1;
                    __nv_bfloat16 h0 = __float2bfloat16(v0);
                    __nv_bfloat16 h1 = __float2bfloat16(v1);
                    __nv_bfloat162 hp; hp.x = h0; hp.y = h1;
                    __nv_bfloat162 lp;
                    lp.x = __float2bfloat16(v0 - __bfloat162float(h0));
                    lp.y = __float2bfloat16(v1 - __bfloat162float(h1));
                    *reinterpret_cast<__nv_bfloat162*>(&Chi[(size_t)rr * N + col]) = hp;
                    *reinterpret_cast<__nv_bfloat162*>(&Clo[(size_t)rr * N + col]) = lp;
                }
            }
    }
}

// ---------------------------------------------------------------------------
// Elementwise split: X fp32 -> hi/lo bf16 (float4 per thread)
// ---------------------------------------------------------------------------
__global__ __launch_bounds__(256) void split_x(
    const float* __restrict__ X, __nv_bfloat16* __restrict__ Hi,
    __nv_bfloat16* __restrict__ Lo)
{
    const size_t i = ((size_t)blockIdx.x * 256 + threadIdx.x) * 4;
    float4 v = *reinterpret_cast<const float4*>(&X[i]);
    __nv_bfloat16 h0 = __float2bfloat16(v.x), h1 = __float2bfloat16(v.y);
    __nv_bfloat16 h2 = __float2bfloat16(v.z), h3 = __float2bfloat16(v.w);
    __nv_bfloat162 hp0, hp1, lp0, lp1;
    hp0.x = h0; hp0.y = h1; hp1.x = h2; hp1.y = h3;
    lp0.x = __float2bfloat16(v.x - __bfloat162float(h0));
    lp0.y = __float2bfloat16(v.y - __bfloat162float(h1));
    lp1.x = __float2bfloat16(v.z - __bfloat162float(h2));
    lp1.y = __float2bfloat16(v.w - __bfloat162float(h3));
    *reinterpret_cast<__nv_bfloat162*>(&Hi[i]) = hp0;
    *reinterpret_cast<__nv_bfloat162*>(&Hi[i + 2]) = hp1;
    *reinterpret_cast<__nv_bfloat162*>(&Lo[i]) = lp0;
    *reinterpret_cast<__nv_bfloat162*>(&Lo[i + 2]) = lp1;
}

// ---------------------------------------------------------------------------
// W [K=1024][N=1024] fp32 -> transposed split W^T hi/lo [n][k], slot z
// ---------------------------------------------------------------------------
__global__ void wsplit(const float* __restrict__ Wq, const float* __restrict__ Wk,
                       const float* __restrict__ Wv,
                       __nv_bfloat16* __restrict__ Thi, __nv_bfloat16* __restrict__ Tlo)
{
    __shared__ float tile[32][33];
    const int z = blockIdx.z;
    const float* W = (z == 0) ? Wq : (z == 1) ? Wk : Wv;
    const int n0 = blockIdx.x * 32, k0 = blockIdx.y * 32;
    const int tx = threadIdx.x, ty = threadIdx.y;
    #pragma unroll
    for (int i = 0; i < 32; i += 8)
        tile[ty + i][tx] = W[(size_t)(k0 + ty + i) * DIM + n0 + tx];
    __syncthreads();
    const size_t base = (size_t)z * DIM * DIM;
    #pragma unroll
    for (int i = 0; i < 32; i += 8) {
        float v = tile[tx][ty + i];   // W[k0+tx][n0+ty+i]
        __nv_bfloat16 h = __float2bfloat16(v);
        const size_t o = base + (size_t)(n0 + ty + i) * DIM + k0 + tx;
        Thi[o] = h;
        Tlo[o] = __float2bfloat16(v - __bfloat162float(h));
    }
}

// ---------------------------------------------------------------------------
// V hi/lo [SEQ][DIM] -> V^T hi/lo [DIM][SEQ]
// ---------------------------------------------------------------------------
__global__ void vtrans(const __nv_bfloat16* __restrict__ Vhi,
                       const __nv_bfloat16* __restrict__ Vlo,
                       __nv_bfloat16* __restrict__ Thi,
                       __nv_bfloat16* __restrict__ Tlo)
{
    __shared__ __nv_bfloat16 th[32][33], tl[32][33];
    const int d0 = blockIdx.x * 32, s0 = blockIdx.y * 32;
    const int tx = threadIdx.x, ty = threadIdx.y;
    #pragma unroll
    for (int i = 0; i < 32; i += 8) {
        th[ty + i][tx] = Vhi[(size_t)(s0 + ty + i) * DIM + d0 + tx];
        tl[ty + i][tx] = Vlo[(size_t)(s0 + ty + i) * DIM + d0 + tx];
    }
    __syncthreads();
    #pragma unroll
    for (int i = 0; i < 32; i += 8) {
        const size_t o = (size_t)(d0 + ty + i) * SEQ + s0 + tx;
        Thi[o] = th[tx][ty + i];
        Tlo[o] = tl[tx][ty + i];
    }
}

// ---------------------------------------------------------------------------
// Row softmax over S[SEQ,SEQ] -> split bf16 P hi/lo. One block per row.
// ---------------------------------------------------------------------------
__global__ __launch_bounds__(256) void softmax_split(
    float* __restrict__ S, __nv_bfloat16* __restrict__ Phi,
    __nv_bfloat16* __restrict__ Plo)
{
    const size_t rowoff = (size_t)blockIdx.x * SEQ;
    float* p = S + rowoff;
    __shared__ float red[256];
    const int tid = threadIdx.x;

    float m = -INFINITY;
    #pragma unroll
    for (int t = 0; t < 4; t++) {
        float4 v = *reinterpret_cast<const float4*>(&p[tid * 4 + t * 1024]);
        m = fmaxf(m, fmaxf(fmaxf(v.x, v.y), fmaxf(v.z, v.w)));
    }
    red[tid] = m;
    __syncthreads();
    for (int s = 128; s > 0; s >>= 1) {
        if (tid < s) red[tid] = fmaxf(red[tid], red[tid + s]);
        __syncthreads();
    }
    m = red[0];
    __syncthreads();

    float sum = 0.0f;
    #pragma unroll
    for (int t = 0; t < 4; t++) {
        float4 v = *reinterpret_cast<const float4*>(&p[tid * 4 + t * 1024]);
        v.x = expf(v.x - m); v.y = expf(v.y - m);
        v.z = expf(v.z - m); v.w = expf(v.w - m);
        sum += v.x + v.y + v.z + v.w;
        *reinterpret_cast<float4*>(&p[tid * 4 + t * 1024]) = v;
    }
    red[tid] = sum;
    __syncthreads();
    for (int s = 128; s > 0; s >>= 1) {
        if (tid < s) red[tid] += red[tid + s];
        __syncthreads();
    }
    const float inv = 1.0f / red[0];
    __syncthreads();

    #pragma unroll
    for (int t = 0; t < 4; t++) {
        const int i = tid * 4 + t * 1024;
        float4 v = *reinterpret_cast<const float4*>(&p[i]);
        v.x *= inv; v.y *= inv; v.z *= inv; v.w *= inv;
        __nv_bfloat16 h0 = __float2bfloat16(v.x), h1 = __float2bfloat16(v.y);
        __nv_bfloat16 h2 = __float2bfloat16(v.z), h3 = __float2bfloat16(v.w);
        __nv_bfloat162 hp0, hp1, lp0, lp1;
        hp0.x = h0; hp0.y = h1; hp1.x = h2; hp1.y = h3;
        lp0.x = __float2bfloat16(v.x - __bfloat162float(h0));
        lp0.y = __float2bfloat16(v.y - __bfloat162float(h1));
        lp1.x = __float2bfloat16(v.z - __bfloat162float(h2));
        lp1.y = __float2bfloat16(v.w - __bfloat162float(h3));
        *reinterpret_cast<__nv_bfloat162*>(&Phi[rowoff + i]) = hp0;
        *reinterpret_cast<__nv_bfloat162*>(&Phi[rowoff + i + 2]) = hp1;
        *reinterpret_cast<__nv_bfloat162*>(&Plo[rowoff + i]) = lp0;
        *reinterpret_cast<__nv_bfloat162*>(&Plo[rowoff + i + 2]) = lp1;
    }
}

// ---------------------------------------------------------------------------
// Launch
// ---------------------------------------------------------------------------
extern "C" void kernel_launch(void* const* d_in, const int* in_sizes, int n_in,
                              void* d_out, int out_size)
{
    const float* X  = (const float*)d_in[0];
    const float* Wq = (const float*)d_in[1];
    const float* bq = (const float*)d_in[2];
    const float* Wk = (const float*)d_in[3];
    const float* bk = (const float*)d_in[4];
    const float* Wv = (const float*)d_in[5];
    const float* bv = (const float*)d_in[6];
    float* out = (float*)d_out;

    __nv_bfloat16 *Xhi, *Xlo, *Wthi, *Wtlo, *QKVhi, *QKVlo, *Vthi, *Vtlo, *Phi, *Plo;
    float* S;
    cudaGetSymbolAddress((void**)&Xhi, g_Xhi);
    cudaGetSymbolAddress((void**)&Xlo, g_Xlo);
    cudaGetSymbolAddress((void**)&Wthi, g_Wthi);
    cudaGetSymbolAddress((void**)&Wtlo, g_Wtlo);
    cudaGetSymbolAddress((void**)&QKVhi, g_QKVhi);
    cudaGetSymbolAddress((void**)&QKVlo, g_QKVlo);
    cudaGetSymbolAddress((void**)&Vthi, g_Vthi);
    cudaGetSymbolAddress((void**)&Vtlo, g_Vtlo);
    cudaGetSymbolAddress((void**)&S, g_S);
    cudaGetSymbolAddress((void**)&Phi, g_Phi);
    cudaGetSymbolAddress((void**)&Plo, g_Plo);

    cudaFuncSetAttribute(hmma_gemm<0>, cudaFuncAttributeMaxDynamicSharedMemorySize, SMEM_BYTES);
    cudaFuncSetAttribute(hmma_gemm<1>, cudaFuncAttributeMaxDynamicSharedMemorySize, SMEM_BYTES);

    // 1) split X
    split_x<<<SEQ * DIM / 1024, 256>>>(X, Xhi, Xlo);
    // 2) transpose+split weights into slots
    wsplit<<<dim3(DIM / 32, DIM / 32, 3), dim3(32, 8)>>>(Wq, Wk, Wv, Wthi, Wtlo);
    // 3) QKV projections (fused over z), split epilogue with bias
    hmma_gemm<1><<<dim3(DIM / 128, SEQ / 128, 3), 256, SMEM_BYTES>>>(
        Xhi, Xlo, Wthi, Wtlo, bq, bk, bv,
        nullptr, QKVhi, QKVlo,
        SEQ, DIM, DIM, 1.0f, (size_t)DIM * DIM, (size_t)SEQ * DIM);
    // 4) transpose V hi/lo
    vtrans<<<dim3(DIM / 32, SEQ / 32), dim3(32, 8)>>>(
        QKVhi + 2 * (size_t)SEQ * DIM, QKVlo + 2 * (size_t)SEQ * DIM, Vthi, Vtlo);
    // 5) S = (Q @ K^T) / 32
    hmma_gemm<0><<<dim3(SEQ / 128, SEQ / 128, 1), 256, SMEM_BYTES>>>(
        QKVhi, QKVlo, QKVhi + (size_t)SEQ * DIM, QKVlo + (size_t)SEQ * DIM,
        nullptr, nullptr, nullptr, S, nullptr, nullptr,
        SEQ, SEQ, DIM, 1.0f / 32.0f, 0, 0);
    // 6) softmax + split P
    softmax_split<<<SEQ, 256>>>(S, Phi, Plo);
    // 7) out = P @ V
    hmma_gemm<0><<<dim3(DIM / 128, SEQ / 128, 1), 256, SMEM_BYTES>>>(
        Phi, Plo, Vthi, Vtlo,
        nullptr, nullptr, nullptr, out, nullptr, nullptr,
        SEQ, DIM, SEQ, 1.0f, 0, 0);
}